// round 4
// baseline (speedup 1.0000x reference)
#include <cuda_runtime.h>

#define BB 2
#define SS 2048
#define EE 256
#define HH 32
#define DK 8
#define NTILES (BB*HH*(SS/256))   // 512 work items (bh, 256-query tile)
#define GRID_ATTN (148*3)         // exactly 3 CTAs per SM

// scratch (no allocations allowed)
__device__ float g_qbuf[BB*HH*SS*DK];   // [b*H+h][s][d]  4MB
__device__ float g_ctx [BB*SS*EE];      // [b*S+s][e]     4MB
__device__ unsigned int g_tile_ctr;

typedef unsigned long long u64;

__device__ __forceinline__ u64 pk2(float x, float y){ u64 r; asm("mov.b64 %0, {%1,%2};" : "=l"(r) : "f"(x), "f"(y)); return r; }
__device__ __forceinline__ void upk2(u64 v, float& x, float& y){ asm("mov.b64 {%0,%1}, %2;" : "=f"(x), "=f"(y) : "l"(v)); }
__device__ __forceinline__ u64 fma2_(u64 a, u64 b, u64 c){ u64 d; asm("fma.rn.f32x2 %0, %1, %2, %3;" : "=l"(d) : "l"(a), "l"(b), "l"(c)); return d; }
__device__ __forceinline__ u64 add2_(u64 a, u64 b){ u64 d; asm("add.rn.f32x2 %0, %1, %2;" : "=l"(d) : "l"(a), "l"(b)); return d; }
__device__ __forceinline__ float ex2_(float x){ float r; asm("ex2.approx.f32 %0, %1;" : "=f"(r) : "f"(x)); return r; }

// ---------------------------------------------------------------------------
// Kernel 1: q = cos(x + theta), rearranged to [b,h,s,d]; also resets tile ctr
// ---------------------------------------------------------------------------
__global__ void __launch_bounds__(256) qprep_kernel(const float* __restrict__ x,
                                                    const float* __restrict__ theta)
{
    if (blockIdx.x == 0 && threadIdx.x == 0) g_tile_ctr = 0u;
    int idx = blockIdx.x * 256 + threadIdx.x;      // over B*S*E = 1,048,576
    int e  = idx & (EE-1);
    int bs = idx >> 8;           // b*S + s
    int h  = e >> 3;
    int d  = e & 7;
    int b  = bs >> 11;
    int s  = bs & (SS-1);
    float v = __cosf(x[idx] + theta[d]);
    g_qbuf[(((b*HH + h)*SS) + s)*DK + d] = v;
}

// ---------------------------------------------------------------------------
// Kernel 2: persistent work-stealing attention.
// 444 CTAs x 128 threads; each tile = (head, 256 queries); 2 queries/thread.
// K fully in smem, pair-packed. No running max (|score| <= 2.83).
// ---------------------------------------------------------------------------
__global__ void __launch_bounds__(128) attn_kernel(const int* __restrict__ mask)
{
    extern __shared__ float sm[];
    float* mb = sm;          // 2048 floats: 0 or -1e9
    float* kT = sm + SS;     // 16384 floats  kT[jp*16 + d*2 + half] = K[2jp+half][d]
    __shared__ unsigned int s_tile;

    const int tid = threadIdx.x;
    const float QS = 1.4426950408889634f * 0.35355339059327373f;  // log2e/sqrt(8)

    for (;;) {
        if (tid == 0) s_tile = atomicAdd(&g_tile_ctr, 1u);
        __syncthreads();                 // publishes s_tile; fences prior smem reads
        const unsigned int t = s_tile;
        if (t >= NTILES) return;

        const int bh = t >> 3;           // b*H + h
        const int qt = t & 7;
        const int b  = bh >> 5;
        const int h  = bh & 31;
        const float* qk = g_qbuf + (size_t)bh * SS * DK;

        // fill mask bias + pair-packed K^T
        for (int j = tid; j < SS; j += 128)
            mb[j] = (mask[b*SS + j] != 0) ? 0.0f : -1e9f;
        const float4* qk4 = (const float4*)qk;
        for (int i4 = tid; i4 < SS*DK/4; i4 += 128) {
            float4 v = qk4[i4];
            int j  = i4 >> 1;
            int d0 = (i4 & 1) << 2;
            int base = ((j >> 1) << 4) + (j & 1);
            kT[base + ((d0+0)<<1)] = v.x;
            kT[base + ((d0+1)<<1)] = v.y;
            kT[base + ((d0+2)<<1)] = v.z;
            kT[base + ((d0+3)<<1)] = v.w;
        }
        __syncthreads();

        const int qrow0 = qt*256 + tid;
        const int qrow1 = qrow0 + 128;

        u64 qA[8], qB[8];
        {
            const float4* qa = (const float4*)(qk + qrow0*DK);
            const float4* qb = (const float4*)(qk + qrow1*DK);
            float4 a0 = qa[0], a1 = qa[1], b0 = qb[0], b1 = qb[1];
            float v;
            v=a0.x*QS; qA[0]=pk2(v,v); v=a0.y*QS; qA[1]=pk2(v,v);
            v=a0.z*QS; qA[2]=pk2(v,v); v=a0.w*QS; qA[3]=pk2(v,v);
            v=a1.x*QS; qA[4]=pk2(v,v); v=a1.y*QS; qA[5]=pk2(v,v);
            v=a1.z*QS; qA[6]=pk2(v,v); v=a1.w*QS; qA[7]=pk2(v,v);
            v=b0.x*QS; qB[0]=pk2(v,v); v=b0.y*QS; qB[1]=pk2(v,v);
            v=b0.z*QS; qB[2]=pk2(v,v); v=b0.w*QS; qB[3]=pk2(v,v);
            v=b1.x*QS; qB[4]=pk2(v,v); v=b1.y*QS; qB[5]=pk2(v,v);
            v=b1.z*QS; qB[6]=pk2(v,v); v=b1.w*QS; qB[7]=pk2(v,v);
        }

        u64 accA[8], accB[8];
        #pragma unroll
        for (int d = 0; d < 8; ++d) { accA[d] = 0ull; accB[d] = 0ull; }
        u64 sumA = 0ull, sumB = 0ull;

        const ulonglong2* kTp = (const ulonglong2*)kT;
        const u64* mbp = (const u64*)mb;

        #pragma unroll 2
        for (int jp = 0; jp < SS/2; ++jp) {
            ulonglong2 ka = kTp[jp*4+0];
            ulonglong2 kb = kTp[jp*4+1];
            ulonglong2 kc = kTp[jp*4+2];
            ulonglong2 kd = kTp[jp*4+3];
            u64 m2 = mbp[jp];
            u64 sa = m2, sb = m2;
            sa = fma2_(qA[0], ka.x, sa);  sb = fma2_(qB[0], ka.x, sb);
            sa = fma2_(qA[1], ka.y, sa);  sb = fma2_(qB[1], ka.y, sb);
            sa = fma2_(qA[2], kb.x, sa);  sb = fma2_(qB[2], kb.x, sb);
            sa = fma2_(qA[3], kb.y, sa);  sb = fma2_(qB[3], kb.y, sb);
            sa = fma2_(qA[4], kc.x, sa);  sb = fma2_(qB[4], kc.x, sb);
            sa = fma2_(qA[5], kc.y, sa);  sb = fma2_(qB[5], kc.y, sb);
            sa = fma2_(qA[6], kd.x, sa);  sb = fma2_(qB[6], kd.x, sb);
            sa = fma2_(qA[7], kd.y, sa);  sb = fma2_(qB[7], kd.y, sb);
            float ax, ay, bx, by;
            upk2(sa, ax, ay);  upk2(sb, bx, by);
            u64 pa = pk2(ex2_(ax), ex2_(ay));
            u64 pb = pk2(ex2_(bx), ex2_(by));
            sumA = add2_(sumA, pa);  sumB = add2_(sumB, pb);
            accA[0] = fma2_(pa, ka.x, accA[0]);  accB[0] = fma2_(pb, ka.x, accB[0]);
            accA[1] = fma2_(pa, ka.y, accA[1]);  accB[1] = fma2_(pb, ka.y, accB[1]);
            accA[2] = fma2_(pa, kb.x, accA[2]);  accB[2] = fma2_(pb, kb.x, accB[2]);
            accA[3] = fma2_(pa, kb.y, accA[3]);  accB[3] = fma2_(pb, kb.y, accB[3]);
            accA[4] = fma2_(pa, kc.x, accA[4]);  accB[4] = fma2_(pb, kc.x, accB[4]);
            accA[5] = fma2_(pa, kc.y, accA[5]);  accB[5] = fma2_(pb, kc.y, accB[5]);
            accA[6] = fma2_(pa, kd.x, accA[6]);  accB[6] = fma2_(pb, kd.x, accB[6]);
            accA[7] = fma2_(pa, kd.y, accA[7]);  accB[7] = fma2_(pb, kd.y, accB[7]);
        }

        {
            float sl, sh;
            upk2(sumA, sl, sh);
            float inv = 1.0f / (sl + sh);
            float* op = g_ctx + ((size_t)(b*SS + qrow0))*EE + h*DK;
            float o[8];
            #pragma unroll
            for (int d = 0; d < 8; ++d) { float x1,x2; upk2(accA[d],x1,x2); o[d]=(x1+x2)*inv; }
            *(float4*)(op)     = make_float4(o[0],o[1],o[2],o[3]);
            *(float4*)(op + 4) = make_float4(o[4],o[5],o[6],o[7]);
        }
        {
            float sl, sh;
            upk2(sumB, sl, sh);
            float inv = 1.0f / (sl + sh);
            float* op = g_ctx + ((size_t)(b*SS + qrow1))*EE + h*DK;
            float o[8];
            #pragma unroll
            for (int d = 0; d < 8; ++d) { float x1,x2; upk2(accB[d],x1,x2); o[d]=(x1+x2)*inv; }
            *(float4*)(op)     = make_float4(o[0],o[1],o[2],o[3]);
            *(float4*)(op + 4) = make_float4(o[4],o[5],o[6],o[7]);
        }
    }
}

// ---------------------------------------------------------------------------
// Kernel 3: out = ctx @ W^T + b.   ctx: [4096,256], W: [256,256] row-major.
// 64x64 tile, BK=16, 256 threads, 4x4 microtile (strided-m to avoid conflicts)
// ---------------------------------------------------------------------------
__global__ void __launch_bounds__(256) outproj_kernel(const float* __restrict__ W,
                                                      const float* __restrict__ bias,
                                                      float* __restrict__ out)
{
    __shared__ float As[16][64];
    __shared__ float Bs[16][64];
    const int tid = threadIdx.x;
    const int m0 = blockIdx.x * 64;
    const int n0 = blockIdx.y * 64;
    const int lr = tid >> 2;            // 0..63
    const int lc = (tid & 3) << 2;      // 0,4,8,12
    const int ty = tid & 15;            // m lane (strided by 16)
    const int tx = tid >> 4;            // n group (contiguous x4)

    float acc[4][4] = {};

    for (int k0 = 0; k0 < EE; k0 += 16) {
        float4 a = *(const float4*)&g_ctx[(size_t)(m0 + lr)*EE + k0 + lc];
        As[lc+0][lr] = a.x; As[lc+1][lr] = a.y; As[lc+2][lr] = a.z; As[lc+3][lr] = a.w;
        float4 w = *(const float4*)&W[(size_t)(n0 + lr)*EE + k0 + lc];
        Bs[lc+0][lr] = w.x; Bs[lc+1][lr] = w.y; Bs[lc+2][lr] = w.z; Bs[lc+3][lr] = w.w;
        __syncthreads();
        #pragma unroll
        for (int k = 0; k < 16; ++k) {
            float a0 = As[k][ty], a1 = As[k][ty+16], a2 = As[k][ty+32], a3 = As[k][ty+48];
            float4 b4 = *(const float4*)&Bs[k][tx << 2];
            acc[0][0] += a0*b4.x; acc[0][1] += a0*b4.y; acc[0][2] += a0*b4.z; acc[0][3] += a0*b4.w;
            acc[1][0] += a1*b4.x; acc[1][1] += a1*b4.y; acc[1][2] += a1*b4.z; acc[1][3] += a1*b4.w;
            acc[2][0] += a2*b4.x; acc[2][1] += a2*b4.y; acc[2][2] += a2*b4.z; acc[2][3] += a2*b4.w;
            acc[3][0] += a3*b4.x; acc[3][1] += a3*b4.y; acc[3][2] += a3*b4.z; acc[3][3] += a3*b4.w;
        }
        __syncthreads();
    }

    float4 bb = *(const float4*)&bias[n0 + (tx << 2)];
    #pragma unroll
    for (int i = 0; i < 4; ++i) {
        int row = m0 + ty + 16*i;
        float4 o;
        o.x = acc[i][0] + bb.x; o.y = acc[i][1] + bb.y;
        o.z = acc[i][2] + bb.z; o.w = acc[i][3] + bb.w;
        *(float4*)&out[(size_t)row*EE + n0 + (tx << 2)] = o;
    }
}

// ---------------------------------------------------------------------------
extern "C" void kernel_launch(void* const* d_in, const int* in_sizes, int n_in,
                              void* d_out, int out_size)
{
    const float* x     = (const float*)d_in[0];
    const int*   mask  = (const int*)  d_in[1];
    const float* theta = (const float*)d_in[2];
    const float* W_out = (const float*)d_in[3];
    const float* b_out = (const float*)d_in[4];
    float* out = (float*)d_out;

    qprep_kernel<<<(BB*SS*EE)/256, 256>>>(x, theta);

    static int smem_set = 0;
    const int smem = (SS + (SS/2)*16) * (int)sizeof(float);   // 73728
    if (!smem_set) {
        cudaFuncSetAttribute(attn_kernel, cudaFuncAttributeMaxDynamicSharedMemorySize, smem);
        smem_set = 1;
    }
    attn_kernel<<<GRID_ATTN, 128, smem>>>(mask);

    outproj_kernel<<<dim3((BB*SS)/64, EE/64), 256>>>(W_out, b_out, out);
}

// round 7
// speedup vs baseline: 2.0794x; 2.0794x over previous
#include <cuda_runtime.h>
#include <cuda_bf16.h>
#include <stdint.h>

#define BB 2
#define SS 2048
#define EE 256
#define HH 32
#define DK 8
#define NBH (BB*HH)          // 64
#define UNITS (NBH*16)       // 1024 tiles of (bh, 128 queries)
#define KC 128               // keys per chunk
#define CHUNKS (SS/KC)       // 16
#define GRID_ATTN (148*2)

// smem layout (bytes from dynamic base)
#define SMQ_OFF 0
#define SMK_OFF 10240            // 2 x 128*80
#define SMV_OFF 30720            // 2 x 16*272
#define SMEM_TOT 39424

// scratch (no allocations allowed)
__device__ __align__(16) unsigned char g_qa[(size_t)NBH*SS*64];   // 8MB  A rows: [qh8|qh8|ql8|1,pad7]
__device__ __align__(16) unsigned char g_kb[(size_t)NBH*SS*64];   // 8MB  B rows: [kh8|kl8|kh8|mb,pad7]
__device__ __align__(16) unsigned char g_vt[(size_t)NBH*CHUNKS*4096]; // 4MB  V^T: [16 n][128 k] bf16/chunk
__device__ float g_ctx[(size_t)BB*SS*EE];                         // 4MB
__device__ unsigned int g_unit_ctr;

__device__ __forceinline__ uint32_t smem_u32(const void* p){
    uint32_t a; asm("{ .reg .u64 t; cvta.to.shared.u64 t, %1; cvt.u32.u64 %0, t; }" : "=r"(a) : "l"(p)); return a; }
__device__ __forceinline__ uint32_t pack_bf(float lo, float hi){
    uint32_t r; asm("cvt.rn.bf16x2.f32 %0, %1, %2;" : "=r"(r) : "f"(hi), "f"(lo)); return r; }
__device__ __forceinline__ float ex2_(float x){ float r; asm("ex2.approx.f32 %0, %1;" : "=f"(r) : "f"(x)); return r; }
__device__ __forceinline__ uint32_t lds32(uint32_t a){
    uint32_t v; asm volatile("ld.shared.b32 %0, [%1];" : "=r"(v) : "r"(a)); return v; }
__device__ __forceinline__ void cpa16(uint32_t saddr, const void* gaddr){
    asm volatile("cp.async.cg.shared.global [%0], [%1], 16;" :: "r"(saddr), "l"(gaddr) : "memory"); }
#define CP_COMMIT() asm volatile("cp.async.commit_group;" ::: "memory")
#define CP_WAIT0()  asm volatile("cp.async.wait_group 0;" ::: "memory")

__device__ __forceinline__ void mma16816(float* c, const uint32_t* a, uint32_t b0, uint32_t b1){
    asm volatile("mma.sync.aligned.m16n8k16.row.col.f32.bf16.bf16.f32 "
        "{%0,%1,%2,%3}, {%4,%5,%6,%7}, {%8,%9}, {%0,%1,%2,%3};"
        : "+f"(c[0]), "+f"(c[1]), "+f"(c[2]), "+f"(c[3])
        : "r"(a[0]), "r"(a[1]), "r"(a[2]), "r"(a[3]), "r"(b0), "r"(b1));
}

// ---------------------------------------------------------------------------
// Kernel 1: build A rows, B rows, V^T chunks from x/theta/mask
// ---------------------------------------------------------------------------
__global__ void __launch_bounds__(256) qprep_kernel(const float* __restrict__ x,
                                                    const int* __restrict__ mask,
                                                    const float* __restrict__ theta)
{
    if (blockIdx.x == 0 && threadIdx.x == 0) g_unit_ctr = 0u;
    int idx = blockIdx.x * 256 + threadIdx.x;     // 131072 = (bh, s)
    int bh = idx >> 11, s = idx & (SS-1);
    int b  = bh >> 5,  h = bh & 31;
    const float* xp = x + ((size_t)(b*SS + s)*EE + h*DK);
    float4 xa = *(const float4*)xp;
    float4 xb = *(const float4*)(xp + 4);
    float y[8];
    y[0]=__cosf(xa.x+theta[0]); y[1]=__cosf(xa.y+theta[1]);
    y[2]=__cosf(xa.z+theta[2]); y[3]=__cosf(xa.w+theta[3]);
    y[4]=__cosf(xb.x+theta[4]); y[5]=__cosf(xb.y+theta[5]);
    y[6]=__cosf(xb.z+theta[6]); y[7]=__cosf(xb.w+theta[7]);

    const float QS = 1.4426950408889634f * 0.35355339059327373f;  // log2e/sqrt(8)
    uint32_t qh[4], ql[4], kh[4], kl[4];
    #pragma unroll
    for (int i = 0; i < 4; ++i) {
        float f0 = y[2*i]*QS, f1 = y[2*i+1]*QS;
        float h0 = __bfloat162float(__float2bfloat16(f0));
        float h1 = __bfloat162float(__float2bfloat16(f1));
        qh[i] = pack_bf(h0, h1);
        ql[i] = pack_bf(f0 - h0, f1 - h1);
        float g0 = y[2*i], g1 = y[2*i+1];
        float e0 = __bfloat162float(__float2bfloat16(g0));
        float e1 = __bfloat162float(__float2bfloat16(g1));
        kh[i] = pack_bf(e0, e1);
        kl[i] = pack_bf(g0 - e0, g1 - e1);
    }
    float mbv = (mask[b*SS + s] != 0) ? 0.0f : -1e9f;

    unsigned char* qa = g_qa + (size_t)idx * 64;
    unsigned char* kb = g_kb + (size_t)idx * 64;
    *(uint4*)(qa +  0) = make_uint4(qh[0], qh[1], qh[2], qh[3]);
    *(uint4*)(qa + 16) = make_uint4(qh[0], qh[1], qh[2], qh[3]);
    *(uint4*)(qa + 32) = make_uint4(ql[0], ql[1], ql[2], ql[3]);
    *(uint4*)(qa + 48) = make_uint4(pack_bf(1.0f, 0.0f), 0u, 0u, 0u);
    *(uint4*)(kb +  0) = make_uint4(kh[0], kh[1], kh[2], kh[3]);
    *(uint4*)(kb + 16) = make_uint4(kl[0], kl[1], kl[2], kl[3]);
    *(uint4*)(kb + 32) = make_uint4(kh[0], kh[1], kh[2], kh[3]);
    *(uint4*)(kb + 48) = make_uint4(pack_bf(mbv, 0.0f), 0u, 0u, 0u);

    unsigned char* vb = g_vt + ((size_t)bh*CHUNKS + (s >> 7)) * 4096;
    int ki = s & 127;
    #pragma unroll
    for (int d = 0; d < 8; ++d)
        *(__nv_bfloat16*)(vb + d*256 + ki*2) = __float2bfloat16(y[d]);
    *(__nv_bfloat16*)(vb + 8*256 + ki*2) = __float2bfloat16(1.0f);
    #pragma unroll
    for (int d = 9; d < 16; ++d)
        *(__nv_bfloat16*)(vb + d*256 + ki*2) = __float2bfloat16(0.0f);
}

// ---------------------------------------------------------------------------
// Kernel 2: persistent mma.sync flash attention. 8 warps x 16 q-rows = 128q.
// ---------------------------------------------------------------------------
__global__ void __launch_bounds__(256, 2) attn_kernel()
{
    extern __shared__ __align__(16) unsigned char smraw[];
    const uint32_t smb = smem_u32(smraw);
    const uint32_t smQ = smb + SMQ_OFF;
    __shared__ unsigned s_unit;

    const int tid  = threadIdx.x;
    const int warp = tid >> 5, lane = tid & 31;
    const int lr = lane >> 2, lj = lane & 3;

    for (;;) {
        if (tid == 0) s_unit = atomicAdd(&g_unit_ctr, 1u);
        __syncthreads();
        const unsigned u = s_unit;
        if (u >= UNITS) return;

        const int bh = u >> 4, qt = u & 15;
        const int b = bh >> 5, h = bh & 31;
        const unsigned char* gq = g_qa + ((size_t)bh*SS + qt*128) * 64;
        const unsigned char* gk = g_kb + (size_t)bh*SS * 64;
        const unsigned char* gv = g_vt + (size_t)bh*CHUNKS * 4096;

        // group 0: Q tile + chunk 0 (K + V^T)
        #pragma unroll
        for (int i = 0; i < 2; ++i) {
            int t = tid + i*256;                   // 512 x 16B
            int row = t >> 2, seg = t & 3;
            cpa16(smQ + row*80 + seg*16, gq + row*64 + seg*16);
            cpa16(smb + SMK_OFF + row*80 + seg*16, gk + row*64 + seg*16);
        }
        { int row = tid >> 4, seg = tid & 15;      // 256 x 16B
          cpa16(smb + SMV_OFF + row*272 + seg*16, gv + row*256 + seg*16); }
        CP_COMMIT();

        uint32_t qf[2][4];
        float accD[2][4] = {{0,0,0,0},{0,0,0,0}};

        for (int c = 0; c < CHUNKS; ++c) {
            const int buf = c & 1;
            CP_WAIT0();
            __syncthreads();

            if (c == 0) {
                uint32_t qb = smQ + (warp*16 + lr)*80 + lj*4;
                qf[0][0] = lds32(qb);       qf[0][1] = lds32(qb + 640);
                qf[0][2] = lds32(qb + 16);  qf[0][3] = lds32(qb + 656);
                qf[1][0] = lds32(qb + 32);  qf[1][1] = lds32(qb + 672);
                qf[1][2] = lds32(qb + 48);  qf[1][3] = lds32(qb + 688);
            }
            if (c < CHUNKS-1) {            // prefetch chunk c+1 into other buffer
                const unsigned char* gkc = gk + (size_t)(c+1)*KC*64;
                const unsigned char* gvc = gv + (size_t)(c+1)*4096;
                uint32_t dK = smb + SMK_OFF + (buf^1)*10240;
                uint32_t dV = smb + SMV_OFF + (buf^1)*4352;
                #pragma unroll
                for (int i = 0; i < 2; ++i) {
                    int t = tid + i*256;
                    int row = t >> 2, seg = t & 3;
                    cpa16(dK + row*80 + seg*16, gkc + row*64 + seg*16);
                }
                { int row = tid >> 4, seg = tid & 15;
                  cpa16(dV + row*272 + seg*16, gvc + row*256 + seg*16); }
                CP_COMMIT();
            }

            // ---- S = A·B, exp immediately per n-tile (keeps sc live set tiny) ----
            uint32_t p[32];
            const uint32_t kbase = smb + SMK_OFF + buf*10240 + lr*80 + lj*4;
            #pragma unroll
            for (int nt = 0; nt < 16; ++nt) {
                float sc[4] = {0.f, 0.f, 0.f, 0.f};
                uint32_t a0 = kbase + nt*640;
                uint32_t b0 = lds32(a0),      b1 = lds32(a0 + 16);
                uint32_t b2 = lds32(a0 + 32), b3 = lds32(a0 + 48);
                mma16816(sc, qf[0], b0, b1);
                mma16816(sc, qf[1], b2, b3);
                p[2*nt]   = pack_bf(ex2_(sc[0]), ex2_(sc[1]));
                p[2*nt+1] = pack_bf(ex2_(sc[2]), ex2_(sc[3]));
            }
            // ---- D += P·V  (V^T rows: 8 value dims + ones row) ----
            const uint32_t vbase = smb + SMV_OFF + buf*4352 + lr*272 + lj*4;
            #pragma unroll
            for (int kt = 0; kt < 8; ++kt) {
                uint32_t v0 = lds32(vbase + kt*32),        v1 = lds32(vbase + kt*32 + 16);
                uint32_t w0 = lds32(vbase + 2176 + kt*32), w1 = lds32(vbase + 2176 + kt*32 + 16);
                mma16816(accD[0], &p[4*kt], v0, v1);
                mma16816(accD[1], &p[4*kt], w0, w1);
            }
        }

        // ---- epilogue: normalize by rowsum (D col 8) and store ----
        float rs0 = __shfl_sync(0xffffffffu, accD[1][0], lane & ~3);
        float rs1 = __shfl_sync(0xffffffffu, accD[1][2], lane & ~3);
        float inv0 = 1.0f / rs0, inv1 = 1.0f / rs1;
        int row0 = qt*128 + warp*16 + lr;
        float* o0 = g_ctx + (size_t)(b*SS + row0)*EE + h*DK + lj*2;
        float* o1 = g_ctx + (size_t)(b*SS + row0 + 8)*EE + h*DK + lj*2;
        *(float2*)o0 = make_float2(accD[0][0]*inv0, accD[0][1]*inv0);
        *(float2*)o1 = make_float2(accD[0][2]*inv1, accD[0][3]*inv1);
    }
}

// ---------------------------------------------------------------------------
// Kernel 3: out = ctx @ W^T + b.
// ---------------------------------------------------------------------------
__global__ void __launch_bounds__(256) outproj_kernel(const float* __restrict__ W,
                                                      const float* __restrict__ bias,
                                                      float* __restrict__ out)
{
    __shared__ float As[16][64];
    __shared__ float Bs[16][64];
    const int tid = threadIdx.x;
    const int m0 = blockIdx.x * 64;
    const int n0 = blockIdx.y * 64;
    const int lr = tid >> 2;
    const int lc = (tid & 3) << 2;
    const int ty = tid & 15;
    const int tx = tid >> 4;

    float acc[4][4] = {};

    for (int k0 = 0; k0 < EE; k0 += 16) {
        float4 a = *(const float4*)&g_ctx[(size_t)(m0 + lr)*EE + k0 + lc];
        As[lc+0][lr] = a.x; As[lc+1][lr] = a.y; As[lc+2][lr] = a.z; As[lc+3][lr] = a.w;
        float4 w = *(const float4*)&W[(size_t)(n0 + lr)*EE + k0 + lc];
        Bs[lc+0][lr] = w.x; Bs[lc+1][lr] = w.y; Bs[lc+2][lr] = w.z; Bs[lc+3][lr] = w.w;
        __syncthreads();
        #pragma unroll
        for (int k = 0; k < 16; ++k) {
            float a0 = As[k][ty], a1 = As[k][ty+16], a2 = As[k][ty+32], a3 = As[k][ty+48];
            float4 b4 = *(const float4*)&Bs[k][tx << 2];
            acc[0][0] += a0*b4.x; acc[0][1] += a0*b4.y; acc[0][2] += a0*b4.z; acc[0][3] += a0*b4.w;
            acc[1][0] += a1*b4.x; acc[1][1] += a1*b4.y; acc[1][2] += a1*b4.z; acc[1][3] += a1*b4.w;
            acc[2][0] += a2*b4.x; acc[2][1] += a2*b4.y; acc[2][2] += a2*b4.z; acc[2][3] += a2*b4.w;
            acc[3][0] += a3*b4.x; acc[3][1] += a3*b4.y; acc[3][2] += a3*b4.z; acc[3][3] += a3*b4.w;
        }
        __syncthreads();
    }

    float4 bb = *(const float4*)&bias[n0 + (tx << 2)];
    #pragma unroll
    for (int i = 0; i < 4; ++i) {
        int row = m0 + ty + 16*i;
        float4 o;
        o.x = acc[i][0] + bb.x; o.y = acc[i][1] + bb.y;
        o.z = acc[i][2] + bb.z; o.w = acc[i][3] + bb.w;
        *(float4*)&out[(size_t)row*EE + n0 + (tx << 2)] = o;
    }
}

// ---------------------------------------------------------------------------
extern "C" void kernel_launch(void* const* d_in, const int* in_sizes, int n_in,
                              void* d_out, int out_size)
{
    const float* x     = (const float*)d_in[0];
    const int*   mask  = (const int*)  d_in[1];
    const float* theta = (const float*)d_in[2];
    const float* W_out = (const float*)d_in[3];
    const float* b_out = (const float*)d_in[4];
    float* out = (float*)d_out;

    qprep_kernel<<<(NBH*SS)/256, 256>>>(x, mask, theta);
    attn_kernel<<<GRID_ATTN, 256, SMEM_TOT>>>();
    outproj_kernel<<<dim3((BB*SS)/64, EE/64), 256>>>(W_out, b_out, out);
}